// round 7
// baseline (speedup 1.0000x reference)
#include <cuda_runtime.h>
#include <cstdint>
#include <cstddef>

#define B_ 8
#define N_ 16384
#define S_ 1024
#define K_ 32
#define NCC (B_*S_)                 // 8192 centers
#define NROWS (NCC*K_)              // 262144 grouped rows
#define R2_ 0.04f
#define CBLKS (NROWS/64)            // 4096 conv blocks (64 rows each)

// ---------------- device scratch (static; allocation APIs banned) ----------------
__device__ __align__(16) float g_centers[NCC*3];
__device__ int                 g_nbr[NROWS];
__device__ __align__(16) float g_h1[(size_t)NROWS*64];          // 64 MiB (reused sem/geo)
__device__ __align__(16) float g_sum[(size_t)128*CBLKS];        // channel-major partial sums
__device__ __align__(16) float g_ssq[(size_t)128*CBLKS];        // channel-major partial sumsq
__device__ __align__(16) float g_mx[(size_t)NCC*128];           // per-center raw-h2 max
__device__ __align__(16) float g_mn[(size_t)NCC*128];           // per-center raw-h2 min
__device__ __align__(16) float g_a[128];                        // BN scale
__device__ __align__(16) float g_c[128];                        // BN shift

// ---------------- cluster SMEM helpers ----------------
__device__ __forceinline__ uint32_t s2u(const void* p) {
    return (uint32_t)__cvta_generic_to_shared(p);
}
__device__ __forceinline__ uint32_t mapa_u32(uint32_t a, int r) {
    uint32_t ret;
    asm("mapa.shared::cluster.u32 %0, %1, %2;" : "=r"(ret) : "r"(a), "r"(r));
    return ret;
}
__device__ __forceinline__ void st_rem64(uint32_t a, unsigned long long v) {
    asm volatile("st.shared::cluster.u64 [%0], %1;" :: "r"(a), "l"(v) : "memory");
}
__device__ __forceinline__ void st_rem32(uint32_t a, uint32_t v) {
    asm volatile("st.shared::cluster.b32 [%0], %1;" :: "r"(a), "r"(v) : "memory");
}
__device__ __forceinline__ void mbar_init(uint32_t a, uint32_t cnt) {
    asm volatile("mbarrier.init.shared.b64 [%0], %1;" :: "r"(a), "r"(cnt) : "memory");
}
__device__ __forceinline__ void mbar_arrive_cluster(uint32_t a) {
    asm volatile("mbarrier.arrive.release.cluster.shared::cluster.b64 _, [%0];"
                 :: "r"(a) : "memory");
}
__device__ __forceinline__ void mbar_wait(uint32_t a, uint32_t parity) {
    uint32_t done;
    asm volatile(
        "{\n\t.reg .pred P;\n\t"
        "mbarrier.try_wait.parity.acquire.cluster.shared::cta.b64 P, [%1], %2, 0x989680;\n\t"
        "selp.b32 %0, 1, 0, P;\n\t}"
        : "=r"(done) : "r"(a), "r"(parity) : "memory");
    while (!done) {
        asm volatile(
            "{\n\t.reg .pred P;\n\t"
            "mbarrier.try_wait.parity.acquire.cluster.shared::cta.b64 P, [%1], %2, 0x989680;\n\t"
            "selp.b32 %0, 1, 0, P;\n\t}"
            : "=r"(done) : "r"(a), "r"(parity) : "memory");
    }
}

// =====================================================================
// FPS: 8-CTA cluster per batch, 512 thr/CTA, 4 points/thread in regs.
// redux.sync warp reductions + mbarrier cross-CTA exchange per step.
// Selection order identical to u64-key method: max dist, then min index.
// =====================================================================
#define FPS_C 8
#define FPS_T 512

__global__ __launch_bounds__(FPS_T, 1) __cluster_dims__(FPS_C, 1, 1)
void fps_kernel(const float* __restrict__ pos) {
    __shared__ unsigned wdist[16];
    __shared__ unsigned widx[16];
    __shared__ float wxs[16], wys[16], wzs[16];
    __shared__ unsigned long long skey[2][FPS_C];   // dist<<32 | (N-idx)
    __shared__ unsigned long long sxy[2][FPS_C];    // (ybits<<32)|xbits
    __shared__ unsigned szf[2][FPS_C];              // zbits
    __shared__ __align__(8) unsigned long long mbar[2];

    const int rank = blockIdx.x & (FPS_C - 1);
    const int b    = blockIdx.x >> 3;
    const int tid  = threadIdx.x;
    const int lane = tid & 31, wid = tid >> 5;
    const float* p = pos + (size_t)b * N_ * 3;

    if (tid == 0) {
        mbar_init(s2u(&mbar[0]), FPS_C);
        mbar_init(s2u(&mbar[1]), FPS_C);
    }
    __syncthreads();
    asm volatile("barrier.cluster.arrive.aligned;" ::: "memory");
    asm volatile("barrier.cluster.wait.aligned;"   ::: "memory");

    float qx[4], qy[4], qz[4], dist[4];
#pragma unroll
    for (int j = 0; j < 4; j++) {
        int g = rank * 2048 + j * FPS_T + tid;
        qx[j] = p[g*3]; qy[j] = p[g*3+1]; qz[j] = p[g*3+2];
        dist[j] = 1e10f;
    }
    float cx = p[0], cy = p[1], cz = p[2];   // far_0 = 0
    int ph0 = 0, ph1 = 0;

    for (int s = 0; s < S_; s++) {
        if (rank == 0 && tid == 0) {
            size_t cc = (size_t)b * S_ + s;
            g_centers[cc*3+0] = cx; g_centers[cc*3+1] = cy; g_centers[cc*3+2] = cz;
        }
        if (s == S_ - 1) break;

        // ---- update dists + per-thread argmax (strict > => smallest idx on tie) ----
        float best = -1.0f, bx = 0.f, by = 0.f, bz = 0.f;
        int bidx = 0;
#pragma unroll
        for (int j = 0; j < 4; j++) {
            float dx = qx[j] - cx, dy = qy[j] - cy, dz = qz[j] - cz;
            float d  = fmaf(dz, dz, fmaf(dy, dy, dx * dx));
            float nd = fminf(dist[j], d);
            dist[j]  = nd;
            if (nd > best) { best = nd; bx = qx[j]; by = qy[j]; bz = qz[j];
                             bidx = rank * 2048 + j * FPS_T + tid; }
        }

        // ---- warp reduce: max dist bits, then min idx among holders ----
        unsigned db = __float_as_uint(best);   // dist >= 0 => bits order-isomorphic
        unsigned wd = __reduce_max_sync(0xFFFFFFFFu, db);
        unsigned cand = (db == wd) ? (unsigned)bidx : 0xFFFFFFFFu;
        unsigned wi = __reduce_min_sync(0xFFFFFFFFu, cand);
        if (db == wd && (unsigned)bidx == wi) {   // unique owner lane (idx unique)
            wdist[wid] = wd; widx[wid] = wi;
            wxs[wid] = bx; wys[wid] = by; wzs[wid] = bz;
        }
        __syncthreads();

        const int bn = (s + 1) & 1;
        if (tid < 32) {
            unsigned d2 = (lane < 16) ? wdist[lane] : 0u;
            unsigned i2 = (lane < 16) ? widx[lane]  : 0xFFFFFFFFu;
            unsigned wd2 = __reduce_max_sync(0xFFFFFFFFu, d2);
            unsigned c2  = (d2 == wd2) ? i2 : 0xFFFFFFFFu;
            unsigned wi2 = __reduce_min_sync(0xFFFFFFFFu, c2);
            if (lane < 16 && d2 == wd2 && i2 == wi2) {   // unique CTA owner
                unsigned long long key =
                    ((unsigned long long)wd2 << 32) | (unsigned)(N_ - (int)wi2);
                unsigned long long xy =
                    ((unsigned long long)__float_as_uint(wys[lane]) << 32)
                    | __float_as_uint(wxs[lane]);
                unsigned zb = __float_as_uint(wzs[lane]);
                uint32_t ak  = s2u(&skey[bn][rank]);
                uint32_t axy = s2u(&sxy[bn][rank]);
                uint32_t az  = s2u(&szf[bn][rank]);
                uint32_t am  = s2u(&mbar[bn]);
#pragma unroll
                for (int r = 0; r < FPS_C; r++) {
                    st_rem64(mapa_u32(ak, r), key);
                    st_rem64(mapa_u32(axy, r), xy);
                    st_rem32(mapa_u32(az, r), zb);
                }
#pragma unroll
                for (int r = 0; r < FPS_C; r++)
                    mbar_arrive_cluster(mapa_u32(am, r));
            }
        }

        // ---- all threads wait local mbar, then combine the 8 records ----
        unsigned par = bn ? ph1 : ph0;
        mbar_wait(s2u(&mbar[bn]), par);
        if (bn) ph1 ^= 1; else ph0 ^= 1;

        unsigned long long kb = skey[bn][0];
        int rb = 0;
#pragma unroll
        for (int r = 1; r < FPS_C; r++) {
            unsigned long long k2 = skey[bn][r];
            if (k2 > kb) { kb = k2; rb = r; }
        }
        unsigned long long xy = sxy[bn][rb];
        cx = __uint_as_float((unsigned)(xy & 0xFFFFFFFFull));
        cy = __uint_as_float((unsigned)(xy >> 32));
        cz = __uint_as_float(szf[bn][rb]);
    }

    asm volatile("barrier.cluster.arrive.aligned;" ::: "memory");
    asm volatile("barrier.cluster.wait.aligned;"   ::: "memory");
}

// =====================================================================
// Ball query: one warp per center, ascending index scan, early exit.
// =====================================================================
__global__ __launch_bounds__(256)
void ballquery_kernel(const float* __restrict__ pos) {
    __shared__ int buf[8][32];
    const int wloc = threadIdx.x >> 5;
    const int lane = threadIdx.x & 31;
    const int cc = blockIdx.x * 8 + wloc;
    const int b = cc >> 10;
    const float* p = pos + (size_t)b * N_ * 3;
    const float cx = g_centers[cc*3], cy = g_centers[cc*3+1], cz = g_centers[cc*3+2];

    int count = 0, first = 0;
    bool haveFirst = false;
    for (int base = 0; base < N_; base += 32) {
        int j = base + lane;
        float x = p[j*3], y = p[j*3+1], z = p[j*3+2];
        float dx = cx - x, dy = cy - y, dz = cz - z;
        float d = fmaf(dz, dz, fmaf(dy, dy, dx * dx));
        bool in = (d <= R2_);
        unsigned m = __ballot_sync(0xFFFFFFFFu, in);
        if (m) {
            if (!haveFirst) { first = base + __ffs(m) - 1; haveFirst = true; }
            int slot = count + __popc(m & ((1u << lane) - 1u));
            if (in && slot < 32) buf[wloc][slot] = j;
            count += __popc(m);
            if (count >= 32) break;
        }
    }
    __syncwarp();
    int v = (lane < count) ? buf[wloc][lane] : first;
    g_nbr[(size_t)cc * 32 + lane] = v;
}

// =====================================================================
// conv1: gather + X[64 x CIN] @ W[CIN x 64] + bias -> raw h1.
// Epilogue: per-block per-channel (sum, sumsq), fixed order -> g_sum/g_ssq.
// =====================================================================
template<int CIN, bool GEO>
__global__ __launch_bounds__(256)
void conv1_kernel(const float* __restrict__ feat, const float* __restrict__ pos,
                  const float* __restrict__ W, const float* __restrict__ bias) {
    __shared__ float Xs[64 * CIN];
    __shared__ float Ws[CIN * 64];
    __shared__ float red[16 * 64];
    const int row0 = blockIdx.x * 64;
    const int tid = threadIdx.x;

    for (int i = tid; i < CIN * 64 / 4; i += 256)
        ((float4*)Ws)[i] = ((const float4*)W)[i];

    if (!GEO) {
        for (int i = tid; i < 64 * 16; i += 256) {
            int r = i >> 4, c4 = (i & 15) * 4;
            int row = row0 + r;
            int j = g_nbr[row];
            int b = row >> 15;
            float4 v = *(const float4*)&feat[((size_t)b * N_ + j) * 64 + c4];
            *(float4*)&Xs[r * CIN + c4] = v;
        }
    } else {
        for (int i = tid; i < 64 * CIN; i += 256) {
            int r = i / CIN, c = i - r * CIN;
            int row = row0 + r;
            int cc = row >> 5;
            if (c < 3) {
                Xs[i] = g_centers[cc * 3 + c];
            } else {
                int j = g_nbr[row];
                int b = row >> 15;
                Xs[i] = pos[((size_t)b * N_ + j) * 3 + (c - 3)];
            }
        }
    }
    __syncthreads();

    const int ty = tid >> 4, tx = tid & 15;
    float acc[4][4];
#pragma unroll
    for (int i = 0; i < 4; i++)
#pragma unroll
        for (int j = 0; j < 4; j++) acc[i][j] = 0.0f;

#pragma unroll
    for (int k = 0; k < CIN; k++) {
        float xv[4];
#pragma unroll
        for (int i = 0; i < 4; i++) xv[i] = Xs[(ty * 4 + i) * CIN + k];
        float4 wv = *(const float4*)&Ws[k * 64 + tx * 4];
#pragma unroll
        for (int i = 0; i < 4; i++) {
            acc[i][0] = fmaf(xv[i], wv.x, acc[i][0]);
            acc[i][1] = fmaf(xv[i], wv.y, acc[i][1]);
            acc[i][2] = fmaf(xv[i], wv.z, acc[i][2]);
            acc[i][3] = fmaf(xv[i], wv.w, acc[i][3]);
        }
    }

    float bb[4];
#pragma unroll
    for (int j = 0; j < 4; j++) bb[j] = bias[tx * 4 + j];
    float sl[4] = {0, 0, 0, 0}, ssl[4] = {0, 0, 0, 0};
#pragma unroll
    for (int i = 0; i < 4; i++) {
        int row = row0 + ty * 4 + i;
        float4 hv;
        hv.x = acc[i][0] + bb[0]; hv.y = acc[i][1] + bb[1];
        hv.z = acc[i][2] + bb[2]; hv.w = acc[i][3] + bb[3];
        *(float4*)&g_h1[(size_t)row * 64 + tx * 4] = hv;
        sl[0] += hv.x; ssl[0] += hv.x * hv.x;
        sl[1] += hv.y; ssl[1] += hv.y * hv.y;
        sl[2] += hv.z; ssl[2] += hv.z * hv.z;
        sl[3] += hv.w; ssl[3] += hv.w * hv.w;
    }
#pragma unroll
    for (int j = 0; j < 4; j++) red[ty * 64 + tx * 4 + j] = sl[j];
    __syncthreads();
    float S = 0.0f, SS = 0.0f;
    if (tid < 64) {
#pragma unroll
        for (int t = 0; t < 16; t++) S += red[t * 64 + tid];
    }
    __syncthreads();
#pragma unroll
    for (int j = 0; j < 4; j++) red[ty * 64 + tx * 4 + j] = ssl[j];
    __syncthreads();
    if (tid < 64) {
#pragma unroll
        for (int t = 0; t < 16; t++) SS += red[t * 64 + tid];
        g_sum[(size_t)tid * CBLKS + blockIdx.x] = S;
        g_ssq[(size_t)tid * CBLKS + blockIdx.x] = SS;
    }
}

// =====================================================================
// conv2 (fused): X = relu(a1*h1 + c1); X[64x64] @ W[64x128] + bias.
// h2 never written. Epilogue: channel (sum,sumsq) + per-center max/min.
// =====================================================================
__global__ __launch_bounds__(256)
void conv2_kernel(const float* __restrict__ W, const float* __restrict__ bias) {
    __shared__ float Xs[64 * 64];    // 16 KB (reused as reduce buffer)
    __shared__ float Ws[64 * 128];   // 32 KB
    const int row0 = blockIdx.x * 64;
    const int tid = threadIdx.x;

    for (int i = tid; i < 64 * 128 / 4; i += 256)
        ((float4*)Ws)[i] = ((const float4*)W)[i];
    for (int i = tid; i < 64 * 16; i += 256) {
        int r = i >> 4, c4 = (i & 15) * 4;
        float4 h = *(const float4*)&g_h1[(size_t)(row0 + r) * 64 + c4];
        float4 A = *(const float4*)&g_a[c4];
        float4 C = *(const float4*)&g_c[c4];
        float4 x;
        x.x = fmaxf(0.0f, fmaf(A.x, h.x, C.x));
        x.y = fmaxf(0.0f, fmaf(A.y, h.y, C.y));
        x.z = fmaxf(0.0f, fmaf(A.z, h.z, C.z));
        x.w = fmaxf(0.0f, fmaf(A.w, h.w, C.w));
        *(float4*)&Xs[r * 64 + c4] = x;
    }
    __syncthreads();

    const int ty = tid >> 4, tx = tid & 15;
    float acc[4][8];
#pragma unroll
    for (int i = 0; i < 4; i++)
#pragma unroll
        for (int j = 0; j < 8; j++) acc[i][j] = 0.0f;

#pragma unroll 8
    for (int k = 0; k < 64; k++) {
        float xv[4];
#pragma unroll
        for (int i = 0; i < 4; i++) xv[i] = Xs[(ty * 4 + i) * 64 + k];
        float4 w0 = *(const float4*)&Ws[k * 128 + tx * 8];
        float4 w1 = *(const float4*)&Ws[k * 128 + tx * 8 + 4];
#pragma unroll
        for (int i = 0; i < 4; i++) {
            acc[i][0] = fmaf(xv[i], w0.x, acc[i][0]);
            acc[i][1] = fmaf(xv[i], w0.y, acc[i][1]);
            acc[i][2] = fmaf(xv[i], w0.z, acc[i][2]);
            acc[i][3] = fmaf(xv[i], w0.w, acc[i][3]);
            acc[i][4] = fmaf(xv[i], w1.x, acc[i][4]);
            acc[i][5] = fmaf(xv[i], w1.y, acc[i][5]);
            acc[i][6] = fmaf(xv[i], w1.z, acc[i][6]);
            acc[i][7] = fmaf(xv[i], w1.w, acc[i][7]);
        }
    }

    float bb[8];
#pragma unroll
    for (int j = 0; j < 8; j++) bb[j] = bias[tx * 8 + j];
    float sl[8], ssl[8], mxl[8], mnl[8];
#pragma unroll
    for (int j = 0; j < 8; j++) {
        sl[j] = 0.0f; ssl[j] = 0.0f;
        mxl[j] = -3.402823466e38f; mnl[j] = 3.402823466e38f;
    }
#pragma unroll
    for (int i = 0; i < 4; i++)
#pragma unroll
        for (int j = 0; j < 8; j++) {
            float h = acc[i][j] + bb[j];
            sl[j] += h; ssl[j] += h * h;
            mxl[j] = fmaxf(mxl[j], h); mnl[j] = fminf(mnl[j], h);
        }

    float* red = Xs;
    __syncthreads();

    float S = 0.0f, SS = 0.0f, mA = 0.0f, mB = 0.0f, nA = 0.0f, nB = 0.0f;
#pragma unroll
    for (int j = 0; j < 8; j++) red[ty * 128 + tx * 8 + j] = sl[j];
    __syncthreads();
    if (tid < 128) {
#pragma unroll
        for (int t = 0; t < 16; t++) S += red[t * 128 + tid];
    }
    __syncthreads();
#pragma unroll
    for (int j = 0; j < 8; j++) red[ty * 128 + tx * 8 + j] = ssl[j];
    __syncthreads();
    if (tid < 128) {
#pragma unroll
        for (int t = 0; t < 16; t++) SS += red[t * 128 + tid];
    }
    __syncthreads();
#pragma unroll
    for (int j = 0; j < 8; j++) red[ty * 128 + tx * 8 + j] = mxl[j];
    __syncthreads();
    if (tid < 128) {
        mA = red[0 * 128 + tid]; mB = red[8 * 128 + tid];
#pragma unroll
        for (int t = 1; t < 8; t++) { mA = fmaxf(mA, red[t * 128 + tid]);
                                      mB = fmaxf(mB, red[(8 + t) * 128 + tid]); }
    }
    __syncthreads();
#pragma unroll
    for (int j = 0; j < 8; j++) red[ty * 128 + tx * 8 + j] = mnl[j];
    __syncthreads();
    if (tid < 128) {
        nA = red[0 * 128 + tid]; nB = red[8 * 128 + tid];
#pragma unroll
        for (int t = 1; t < 8; t++) { nA = fminf(nA, red[t * 128 + tid]);
                                      nB = fminf(nB, red[(8 + t) * 128 + tid]); }
        int blk = blockIdx.x;
        g_sum[(size_t)tid * CBLKS + blk] = S;
        g_ssq[(size_t)tid * CBLKS + blk] = SS;
        g_mx[(size_t)(blk * 2 + 0) * 128 + tid] = mA;
        g_mx[(size_t)(blk * 2 + 1) * 128 + tid] = mB;
        g_mn[(size_t)(blk * 2 + 0) * 128 + tid] = nA;
        g_mn[(size_t)(blk * 2 + 1) * 128 + tid] = nB;
    }
}

// =====================================================================
// BN finalize: one block per channel; coalesced channel-major partials;
// fp64 fixed-order reduce -> affine (a, c).
// =====================================================================
__global__ __launch_bounds__(256)
void finalize_stats(const float* __restrict__ gamma,
                    const float* __restrict__ beta, int C) {
    const int ch = blockIdx.x;
    const int t = threadIdx.x;     // 256
    __shared__ double rs[256], rss[256];
    double S = 0.0, SS = 0.0;
#pragma unroll 4
    for (int i = 0; i < 16; i++) {
        int blk = i * 256 + t;     // coalesced + deterministic
        S  += (double)g_sum[(size_t)ch * CBLKS + blk];
        SS += (double)g_ssq[(size_t)ch * CBLKS + blk];
    }
    rs[t] = S; rss[t] = SS;
    __syncthreads();
    for (int off = 128; off; off >>= 1) {
        if (t < off) { rs[t] += rs[t + off]; rss[t] += rss[t + off]; }
        __syncthreads();
    }
    if (t == 0) {
        double inv_n = 1.0 / (double)NROWS;
        double mu  = rs[0] * inv_n;
        double var = rss[0] * inv_n - mu * mu;
        double a = (double)gamma[ch] / sqrt(var + 1e-5);
        g_a[ch] = (float)a;
        g_c[ch] = (float)((double)beta[ch] - mu * a);
    }
}

// =====================================================================
// Output: relu(a * extreme(h2) + c). Affine monotone => commutes with max.
// =====================================================================
__global__ void final_out(float* __restrict__ out) {
    const int cc = blockIdx.x;
    const int ch = threadIdx.x;    // 128
    float a = g_a[ch];
    float ext = (a >= 0.0f) ? g_mx[(size_t)cc * 128 + ch] : g_mn[(size_t)cc * 128 + ch];
    out[(size_t)cc * 128 + ch] = fmaxf(0.0f, fmaf(a, ext, g_c[ch]));
}

// =====================================================================
extern "C" void kernel_launch(void* const* d_in, const int* in_sizes, int n_in,
                              void* d_out, int out_size) {
    const float* pos     = (const float*)d_in[0];
    const float* feat    = (const float*)d_in[1];
    const float* w_sem1  = (const float*)d_in[2];
    const float* b_sem1  = (const float*)d_in[3];
    const float* g_sem1  = (const float*)d_in[4];
    const float* be_sem1 = (const float*)d_in[5];
    const float* w_sem2  = (const float*)d_in[6];
    const float* b_sem2  = (const float*)d_in[7];
    const float* g_sem2  = (const float*)d_in[8];
    const float* be_sem2 = (const float*)d_in[9];
    const float* w_geo1  = (const float*)d_in[10];
    const float* b_geo1  = (const float*)d_in[11];
    const float* g_geo1  = (const float*)d_in[12];
    const float* be_geo1 = (const float*)d_in[13];
    const float* w_geo2  = (const float*)d_in[14];
    const float* b_geo2  = (const float*)d_in[15];
    const float* g_geo2  = (const float*)d_in[16];
    const float* be_geo2 = (const float*)d_in[17];
    float* out = (float*)d_out;

    fps_kernel<<<B_ * FPS_C, FPS_T>>>(pos);
    ballquery_kernel<<<NCC / 8, 256>>>(pos);

    // ---- SEM branch ----
    conv1_kernel<64, false><<<CBLKS, 256>>>(feat, nullptr, w_sem1, b_sem1);
    finalize_stats<<<64, 256>>>(g_sem1, be_sem1, 64);
    conv2_kernel<<<CBLKS, 256>>>(w_sem2, b_sem2);
    finalize_stats<<<128, 256>>>(g_sem2, be_sem2, 128);
    final_out<<<NCC, 128>>>(out);

    // ---- GEO branch (reuses scratch sequentially; stream-ordered) ----
    conv1_kernel<6, true><<<CBLKS, 256>>>(nullptr, pos, w_geo1, b_geo1);
    finalize_stats<<<64, 256>>>(g_geo1, be_geo1, 64);
    conv2_kernel<<<CBLKS, 256>>>(w_geo2, b_geo2);
    finalize_stats<<<128, 256>>>(g_geo2, be_geo2, 128);
    final_out<<<NCC, 128>>>(out + (size_t)NCC * 128);
}

// round 9
// speedup vs baseline: 1.5627x; 1.5627x over previous
#include <cuda_runtime.h>
#include <cstdint>
#include <cstddef>

#define B_ 8
#define N_ 16384
#define S_ 1024
#define K_ 32
#define NCC (B_*S_)                 // 8192 centers
#define NROWS (NCC*K_)              // 262144 grouped rows
#define R2_ 0.04f
#define CBLKS (NROWS/64)            // 4096 conv blocks (64 rows each)

// ---------------- device scratch (static; allocation APIs banned) ----------------
__device__ __align__(16) float g_centers[NCC*3];
__device__ int                 g_nbr[NROWS];
__device__ __align__(16) float g_h1[(size_t)NROWS*64];          // 64 MiB (reused sem/geo)
__device__ __align__(16) float g_part[(size_t)CBLKS*128*2];     // per-block (sum,sumsq)
__device__ __align__(16) float g_mx[(size_t)NCC*128];           // per-center raw-h2 max
__device__ __align__(16) float g_mn[(size_t)NCC*128];           // per-center raw-h2 min
__device__ __align__(16) float g_a[128];                        // BN scale
__device__ __align__(16) float g_c[128];                        // BN shift

// ---------------- cluster SMEM helpers ----------------
__device__ __forceinline__ uint32_t s2u(const void* p) {
    return (uint32_t)__cvta_generic_to_shared(p);
}
__device__ __forceinline__ uint32_t mapa_u32(uint32_t a, int r) {
    uint32_t ret;
    asm("mapa.shared::cluster.u32 %0, %1, %2;" : "=r"(ret) : "r"(a), "r"(r));
    return ret;
}
__device__ __forceinline__ void st_rem64(uint32_t a, unsigned long long v) {
    asm volatile("st.shared::cluster.u64 [%0], %1;" :: "r"(a), "l"(v) : "memory");
}
__device__ __forceinline__ void st_rem32(uint32_t a, uint32_t v) {
    asm volatile("st.shared::cluster.b32 [%0], %1;" :: "r"(a), "r"(v) : "memory");
}
__device__ __forceinline__ void fence_cluster() {
    asm volatile("fence.acq_rel.cluster;" ::: "memory");
}
__device__ __forceinline__ uint4 lds_volatile_v4(const void* p) {
    uint4 v;
    asm volatile("ld.volatile.shared.v4.u32 {%0,%1,%2,%3}, [%4];"
                 : "=r"(v.x), "=r"(v.y), "=r"(v.z), "=r"(v.w)
                 : "r"(s2u(p)));
    return v;
}

// =====================================================================
// FPS: 8-CTA cluster per batch, 512 thr/CTA, 4 points/thread in regs.
// Cross-CTA exchange via DSMEM spin-flags (no barrier.cluster per step,
// no mbarrier). Selection order: max dist, then min index (== u64 key).
// =====================================================================
#define FPS_C 8
#define FPS_T 512

__global__ __launch_bounds__(FPS_T, 1) __cluster_dims__(FPS_C, 1, 1)
void fps_kernel(const float* __restrict__ pos) {
    __shared__ unsigned wdist[16];
    __shared__ unsigned widx[16];
    __shared__ float wxs[16], wys[16], wzs[16];
    __shared__ __align__(16) unsigned long long skey[2][FPS_C]; // dist<<32|(N-idx)
    __shared__ __align__(16) unsigned long long sxy[2][FPS_C];  // (ybits<<32)|xbits
    __shared__ __align__(16) unsigned szf[2][FPS_C];            // zbits
    __shared__ __align__(32) unsigned sflag[FPS_C];             // monotone seq per writer

    const int rank = blockIdx.x & (FPS_C - 1);
    const int b    = blockIdx.x >> 3;
    const int tid  = threadIdx.x;
    const int lane = tid & 31, wid = tid >> 5;
    const float* p = pos + (size_t)b * N_ * 3;

    if (tid < FPS_C) sflag[tid] = 0u;
    __syncthreads();
    // all flags zeroed cluster-wide before any publish
    asm volatile("barrier.cluster.arrive.aligned;" ::: "memory");
    asm volatile("barrier.cluster.wait.aligned;"   ::: "memory");

    float qx[4], qy[4], qz[4], dist[4];
#pragma unroll
    for (int j = 0; j < 4; j++) {
        int g = rank * 2048 + j * FPS_T + tid;
        qx[j] = p[g*3]; qy[j] = p[g*3+1]; qz[j] = p[g*3+2];
        dist[j] = 1e10f;
    }
    float cx = p[0], cy = p[1], cz = p[2];   // far_0 = 0

    for (int s = 0; s < S_; s++) {
        if (rank == 0 && tid == 0) {
            size_t cc = (size_t)b * S_ + s;
            g_centers[cc*3+0] = cx; g_centers[cc*3+1] = cy; g_centers[cc*3+2] = cz;
        }
        if (s == S_ - 1) break;

        // ---- update dists + per-thread argmax (strict > => smallest idx on tie) ----
        float best = -1.0f, bx = 0.f, by = 0.f, bz = 0.f;
        int bidx = 0;
#pragma unroll
        for (int j = 0; j < 4; j++) {
            float dx = qx[j] - cx, dy = qy[j] - cy, dz = qz[j] - cz;
            float d  = fmaf(dz, dz, fmaf(dy, dy, dx * dx));
            float nd = fminf(dist[j], d);
            dist[j]  = nd;
            if (nd > best) { best = nd; bx = qx[j]; by = qy[j]; bz = qz[j];
                             bidx = rank * 2048 + j * FPS_T + tid; }
        }

        // ---- warp reduce: max dist bits, then min idx among holders ----
        unsigned db = __float_as_uint(best);   // dist >= 0 => bits order-isomorphic
        unsigned wd = __reduce_max_sync(0xFFFFFFFFu, db);
        unsigned cand = (db == wd) ? (unsigned)bidx : 0xFFFFFFFFu;
        unsigned wi = __reduce_min_sync(0xFFFFFFFFu, cand);
        if (db == wd && (unsigned)bidx == wi) {   // unique owner lane (idx unique)
            wdist[wid] = wd; widx[wid] = wi;
            wxs[wid] = bx; wys[wid] = by; wzs[wid] = bz;
        }
        // Orders (a) previous iteration's record reads before this publish,
        // (b) wdist/widx/coords stores before warp0 reads them.
        __syncthreads();

        const unsigned seq = (unsigned)s + 1u;
        const int par = (int)(seq & 1u);

        if (wid == 0) {
            unsigned d2 = (lane < 16) ? wdist[lane] : 0u;
            unsigned i2 = (lane < 16) ? widx[lane]  : 0xFFFFFFFFu;
            unsigned wd2 = __reduce_max_sync(0xFFFFFFFFu, d2);
            unsigned c2  = (d2 == wd2) ? i2 : 0xFFFFFFFFu;
            unsigned wi2 = __reduce_min_sync(0xFFFFFFFFu, c2);
            unsigned omask = __ballot_sync(0xFFFFFFFFu,
                                           (lane < 16) && d2 == wd2 && i2 == wi2);
            int owner = __ffs(omask) - 1;          // unique (indices unique)
            if (lane < FPS_C) {
                unsigned long long key =
                    ((unsigned long long)wd2 << 32) | (unsigned)(N_ - (int)wi2);
                unsigned long long xy =
                    ((unsigned long long)__float_as_uint(wys[owner]) << 32)
                    | __float_as_uint(wxs[owner]);
                unsigned zb = __float_as_uint(wzs[owner]);
                // lane r publishes this CTA's record into peer r (parallel fan-out)
                st_rem64(mapa_u32(s2u(&skey[par][rank]), lane), key);
                st_rem64(mapa_u32(s2u(&sxy[par][rank]),  lane), xy);
                st_rem32(mapa_u32(s2u(&szf[par][rank]),  lane), zb);
                fence_cluster();                    // release records before flag
                st_rem32(mapa_u32(s2u(&sflag[rank]),     lane), seq);
            }
        }

        // ---- spin on LOCAL flags until all 8 writers reached seq ----
        for (;;) {
            uint4 f0 = lds_volatile_v4(&sflag[0]);
            uint4 f1 = lds_volatile_v4(&sflag[4]);
            if (f0.x >= seq && f0.y >= seq && f0.z >= seq && f0.w >= seq &&
                f1.x >= seq && f1.y >= seq && f1.z >= seq && f1.w >= seq) break;
        }
        fence_cluster();                            // acquire records

        // ---- combine the 8 published records ----
        unsigned long long kb = skey[par][0];
        int rb = 0;
#pragma unroll
        for (int r = 1; r < FPS_C; r++) {
            unsigned long long k2 = skey[par][r];
            if (k2 > kb) { kb = k2; rb = r; }
        }
        unsigned long long xy = sxy[par][rb];
        cx = __uint_as_float((unsigned)(xy & 0xFFFFFFFFull));
        cy = __uint_as_float((unsigned)(xy >> 32));
        cz = __uint_as_float(szf[par][rb]);
    }

    // DSMEM safety: no CTA exits while peers might still address its SMEM.
    asm volatile("barrier.cluster.arrive.aligned;" ::: "memory");
    asm volatile("barrier.cluster.wait.aligned;"   ::: "memory");
}

// =====================================================================
// Ball query: one warp per center, ascending index scan, early exit.
// =====================================================================
__global__ __launch_bounds__(256)
void ballquery_kernel(const float* __restrict__ pos) {
    __shared__ int buf[8][32];
    const int wloc = threadIdx.x >> 5;
    const int lane = threadIdx.x & 31;
    const int cc = blockIdx.x * 8 + wloc;
    const int b = cc >> 10;
    const float* p = pos + (size_t)b * N_ * 3;
    const float cx = g_centers[cc*3], cy = g_centers[cc*3+1], cz = g_centers[cc*3+2];

    int count = 0, first = 0;
    bool haveFirst = false;
    for (int base = 0; base < N_; base += 32) {
        int j = base + lane;
        float x = p[j*3], y = p[j*3+1], z = p[j*3+2];
        float dx = cx - x, dy = cy - y, dz = cz - z;
        float d = fmaf(dz, dz, fmaf(dy, dy, dx * dx));
        bool in = (d <= R2_);
        unsigned m = __ballot_sync(0xFFFFFFFFu, in);
        if (m) {
            if (!haveFirst) { first = base + __ffs(m) - 1; haveFirst = true; }
            int slot = count + __popc(m & ((1u << lane) - 1u));
            if (in && slot < 32) buf[wloc][slot] = j;
            count += __popc(m);
            if (count >= 32) break;
        }
    }
    __syncwarp();
    int v = (lane < count) ? buf[wloc][lane] : first;
    g_nbr[(size_t)cc * 32 + lane] = v;
}

// =====================================================================
// conv1: gather + X[64 x CIN] @ W[CIN x 64] + bias -> raw h1.
// Epilogue: per-block per-channel (sum, sumsq), fixed order -> g_part.
// =====================================================================
template<int CIN, bool GEO>
__global__ __launch_bounds__(256)
void conv1_kernel(const float* __restrict__ feat, const float* __restrict__ pos,
                  const float* __restrict__ W, const float* __restrict__ bias) {
    __shared__ float Xs[64 * CIN];
    __shared__ float Ws[CIN * 64];
    __shared__ float red[16 * 64];
    const int row0 = blockIdx.x * 64;
    const int tid = threadIdx.x;

    for (int i = tid; i < CIN * 64 / 4; i += 256)
        ((float4*)Ws)[i] = ((const float4*)W)[i];

    if (!GEO) {
        for (int i = tid; i < 64 * 16; i += 256) {
            int r = i >> 4, c4 = (i & 15) * 4;
            int row = row0 + r;
            int j = g_nbr[row];
            int b = row >> 15;
            float4 v = *(const float4*)&feat[((size_t)b * N_ + j) * 64 + c4];
            *(float4*)&Xs[r * CIN + c4] = v;
        }
    } else {
        for (int i = tid; i < 64 * CIN; i += 256) {
            int r = i / CIN, c = i - r * CIN;
            int row = row0 + r;
            int cc = row >> 5;
            if (c < 3) {
                Xs[i] = g_centers[cc * 3 + c];
            } else {
                int j = g_nbr[row];
                int b = row >> 15;
                Xs[i] = pos[((size_t)b * N_ + j) * 3 + (c - 3)];
            }
        }
    }
    __syncthreads();

    const int ty = tid >> 4, tx = tid & 15;
    float acc[4][4];
#pragma unroll
    for (int i = 0; i < 4; i++)
#pragma unroll
        for (int j = 0; j < 4; j++) acc[i][j] = 0.0f;

#pragma unroll
    for (int k = 0; k < CIN; k++) {
        float xv[4];
#pragma unroll
        for (int i = 0; i < 4; i++) xv[i] = Xs[(ty * 4 + i) * CIN + k];
        float4 wv = *(const float4*)&Ws[k * 64 + tx * 4];
#pragma unroll
        for (int i = 0; i < 4; i++) {
            acc[i][0] = fmaf(xv[i], wv.x, acc[i][0]);
            acc[i][1] = fmaf(xv[i], wv.y, acc[i][1]);
            acc[i][2] = fmaf(xv[i], wv.z, acc[i][2]);
            acc[i][3] = fmaf(xv[i], wv.w, acc[i][3]);
        }
    }

    float bb[4];
#pragma unroll
    for (int j = 0; j < 4; j++) bb[j] = bias[tx * 4 + j];
    float sl[4] = {0, 0, 0, 0}, ssl[4] = {0, 0, 0, 0};
#pragma unroll
    for (int i = 0; i < 4; i++) {
        int row = row0 + ty * 4 + i;
        float4 hv;
        hv.x = acc[i][0] + bb[0]; hv.y = acc[i][1] + bb[1];
        hv.z = acc[i][2] + bb[2]; hv.w = acc[i][3] + bb[3];
        *(float4*)&g_h1[(size_t)row * 64 + tx * 4] = hv;
        sl[0] += hv.x; ssl[0] += hv.x * hv.x;
        sl[1] += hv.y; ssl[1] += hv.y * hv.y;
        sl[2] += hv.z; ssl[2] += hv.z * hv.z;
        sl[3] += hv.w; ssl[3] += hv.w * hv.w;
    }
#pragma unroll
    for (int j = 0; j < 4; j++) red[ty * 64 + tx * 4 + j] = sl[j];
    __syncthreads();
    float S = 0.0f, SS = 0.0f;
    if (tid < 64) {
#pragma unroll
        for (int t = 0; t < 16; t++) S += red[t * 64 + tid];
    }
    __syncthreads();
#pragma unroll
    for (int j = 0; j < 4; j++) red[ty * 64 + tx * 4 + j] = ssl[j];
    __syncthreads();
    if (tid < 64) {
#pragma unroll
        for (int t = 0; t < 16; t++) SS += red[t * 64 + tid];
        g_part[((size_t)blockIdx.x * 64 + tid) * 2 + 0] = S;
        g_part[((size_t)blockIdx.x * 64 + tid) * 2 + 1] = SS;
    }
}

// =====================================================================
// conv2 (fused): X = relu(a1*h1 + c1); X[64x64] @ W[64x128] + bias.
// h2 never written. Epilogue: channel (sum,sumsq) + per-center max/min.
// =====================================================================
__global__ __launch_bounds__(256)
void conv2_kernel(const float* __restrict__ W, const float* __restrict__ bias) {
    __shared__ float Xs[64 * 64];    // 16 KB (reused as reduce buffer)
    __shared__ float Ws[64 * 128];   // 32 KB
    const int row0 = blockIdx.x * 64;
    const int tid = threadIdx.x;

    for (int i = tid; i < 64 * 128 / 4; i += 256)
        ((float4*)Ws)[i] = ((const float4*)W)[i];
    for (int i = tid; i < 64 * 16; i += 256) {
        int r = i >> 4, c4 = (i & 15) * 4;
        float4 h = *(const float4*)&g_h1[(size_t)(row0 + r) * 64 + c4];
        float4 A = *(const float4*)&g_a[c4];
        float4 C = *(const float4*)&g_c[c4];
        float4 x;
        x.x = fmaxf(0.0f, fmaf(A.x, h.x, C.x));
        x.y = fmaxf(0.0f, fmaf(A.y, h.y, C.y));
        x.z = fmaxf(0.0f, fmaf(A.z, h.z, C.z));
        x.w = fmaxf(0.0f, fmaf(A.w, h.w, C.w));
        *(float4*)&Xs[r * 64 + c4] = x;
    }
    __syncthreads();

    const int ty = tid >> 4, tx = tid & 15;
    float acc[4][8];
#pragma unroll
    for (int i = 0; i < 4; i++)
#pragma unroll
        for (int j = 0; j < 8; j++) acc[i][j] = 0.0f;

#pragma unroll 8
    for (int k = 0; k < 64; k++) {
        float xv[4];
#pragma unroll
        for (int i = 0; i < 4; i++) xv[i] = Xs[(ty * 4 + i) * 64 + k];
        float4 w0 = *(const float4*)&Ws[k * 128 + tx * 8];
        float4 w1 = *(const float4*)&Ws[k * 128 + tx * 8 + 4];
#pragma unroll
        for (int i = 0; i < 4; i++) {
            acc[i][0] = fmaf(xv[i], w0.x, acc[i][0]);
            acc[i][1] = fmaf(xv[i], w0.y, acc[i][1]);
            acc[i][2] = fmaf(xv[i], w0.z, acc[i][2]);
            acc[i][3] = fmaf(xv[i], w0.w, acc[i][3]);
            acc[i][4] = fmaf(xv[i], w1.x, acc[i][4]);
            acc[i][5] = fmaf(xv[i], w1.y, acc[i][5]);
            acc[i][6] = fmaf(xv[i], w1.z, acc[i][6]);
            acc[i][7] = fmaf(xv[i], w1.w, acc[i][7]);
        }
    }

    float bb[8];
#pragma unroll
    for (int j = 0; j < 8; j++) bb[j] = bias[tx * 8 + j];
    float sl[8], ssl[8], mxl[8], mnl[8];
#pragma unroll
    for (int j = 0; j < 8; j++) {
        sl[j] = 0.0f; ssl[j] = 0.0f;
        mxl[j] = -3.402823466e38f; mnl[j] = 3.402823466e38f;
    }
#pragma unroll
    for (int i = 0; i < 4; i++)
#pragma unroll
        for (int j = 0; j < 8; j++) {
            float h = acc[i][j] + bb[j];
            sl[j] += h; ssl[j] += h * h;
            mxl[j] = fmaxf(mxl[j], h); mnl[j] = fminf(mnl[j], h);
        }

    float* red = Xs;
    __syncthreads();

    float S = 0.0f, SS = 0.0f, mA = 0.0f, mB = 0.0f, nA = 0.0f, nB = 0.0f;
#pragma unroll
    for (int j = 0; j < 8; j++) red[ty * 128 + tx * 8 + j] = sl[j];
    __syncthreads();
    if (tid < 128) {
#pragma unroll
        for (int t = 0; t < 16; t++) S += red[t * 128 + tid];
    }
    __syncthreads();
#pragma unroll
    for (int j = 0; j < 8; j++) red[ty * 128 + tx * 8 + j] = ssl[j];
    __syncthreads();
    if (tid < 128) {
#pragma unroll
        for (int t = 0; t < 16; t++) SS += red[t * 128 + tid];
    }
    __syncthreads();
#pragma unroll
    for (int j = 0; j < 8; j++) red[ty * 128 + tx * 8 + j] = mxl[j];
    __syncthreads();
    if (tid < 128) {
        mA = red[0 * 128 + tid]; mB = red[8 * 128 + tid];
#pragma unroll
        for (int t = 1; t < 8; t++) { mA = fmaxf(mA, red[t * 128 + tid]);
                                      mB = fmaxf(mB, red[(8 + t) * 128 + tid]); }
    }
    __syncthreads();
#pragma unroll
    for (int j = 0; j < 8; j++) red[ty * 128 + tx * 8 + j] = mnl[j];
    __syncthreads();
    if (tid < 128) {
        nA = red[0 * 128 + tid]; nB = red[8 * 128 + tid];
#pragma unroll
        for (int t = 1; t < 8; t++) { nA = fminf(nA, red[t * 128 + tid]);
                                      nB = fminf(nB, red[(8 + t) * 128 + tid]); }
        int blk = blockIdx.x;
        g_part[((size_t)blk * 128 + tid) * 2 + 0] = S;
        g_part[((size_t)blk * 128 + tid) * 2 + 1] = SS;
        g_mx[(size_t)(blk * 2 + 0) * 128 + tid] = mA;
        g_mx[(size_t)(blk * 2 + 1) * 128 + tid] = mB;
        g_mn[(size_t)(blk * 2 + 0) * 128 + tid] = nA;
        g_mn[(size_t)(blk * 2 + 1) * 128 + tid] = nB;
    }
}

// =====================================================================
// BN finalize: one block per channel; fp64 fixed-order tree over 4096
// per-block partials -> affine (a, c).
// =====================================================================
__global__ __launch_bounds__(256)
void finalize_stats(const float* __restrict__ gamma,
                    const float* __restrict__ beta, int C) {
    const int ch = blockIdx.x;
    const int t = threadIdx.x;     // 256
    __shared__ double rs[256], rss[256];
    double S = 0.0, SS = 0.0;
#pragma unroll 4
    for (int i = 0; i < 16; i++) {
        int blk = t * 16 + i;      // fixed order
        S  += (double)g_part[((size_t)blk * C + ch) * 2 + 0];
        SS += (double)g_part[((size_t)blk * C + ch) * 2 + 1];
    }
    rs[t] = S; rss[t] = SS;
    __syncthreads();
    for (int off = 128; off; off >>= 1) {
        if (t < off) { rs[t] += rs[t + off]; rss[t] += rss[t + off]; }
        __syncthreads();
    }
    if (t == 0) {
        double inv_n = 1.0 / (double)NROWS;
        double mu  = rs[0] * inv_n;
        double var = rss[0] * inv_n - mu * mu;
        double a = (double)gamma[ch] / sqrt(var + 1e-5);
        g_a[ch] = (float)a;
        g_c[ch] = (float)((double)beta[ch] - mu * a);
    }
}

// =====================================================================
// Output: relu(a * extreme(h2) + c). Affine monotone => commutes with max.
// =====================================================================
__global__ void final_out(float* __restrict__ out) {
    const int cc = blockIdx.x;
    const int ch = threadIdx.x;    // 128
    float a = g_a[ch];
    float ext = (a >= 0.0f) ? g_mx[(size_t)cc * 128 + ch] : g_mn[(size_t)cc * 128 + ch];
    out[(size_t)cc * 128 + ch] = fmaxf(0.0f, fmaf(a, ext, g_c[ch]));
}

// =====================================================================
extern "C" void kernel_launch(void* const* d_in, const int* in_sizes, int n_in,
                              void* d_out, int out_size) {
    const float* pos     = (const float*)d_in[0];
    const float* feat    = (const float*)d_in[1];
    const float* w_sem1  = (const float*)d_in[2];
    const float* b_sem1  = (const float*)d_in[3];
    const float* g_sem1  = (const float*)d_in[4];
    const float* be_sem1 = (const float*)d_in[5];
    const float* w_sem2  = (const float*)d_in[6];
    const float* b_sem2  = (const float*)d_in[7];
    const float* g_sem2  = (const float*)d_in[8];
    const float* be_sem2 = (const float*)d_in[9];
    const float* w_geo1  = (const float*)d_in[10];
    const float* b_geo1  = (const float*)d_in[11];
    const float* g_geo1  = (const float*)d_in[12];
    const float* be_geo1 = (const float*)d_in[13];
    const float* w_geo2  = (const float*)d_in[14];
    const float* b_geo2  = (const float*)d_in[15];
    const float* g_geo2  = (const float*)d_in[16];
    const float* be_geo2 = (const float*)d_in[17];
    float* out = (float*)d_out;

    fps_kernel<<<B_ * FPS_C, FPS_T>>>(pos);
    ballquery_kernel<<<NCC / 8, 256>>>(pos);

    // ---- SEM branch ----
    conv1_kernel<64, false><<<CBLKS, 256>>>(feat, nullptr, w_sem1, b_sem1);
    finalize_stats<<<64, 256>>>(g_sem1, be_sem1, 64);
    conv2_kernel<<<CBLKS, 256>>>(w_sem2, b_sem2);
    finalize_stats<<<128, 256>>>(g_sem2, be_sem2, 128);
    final_out<<<NCC, 128>>>(out);

    // ---- GEO branch (reuses scratch sequentially; stream-ordered) ----
    conv1_kernel<6, true><<<CBLKS, 256>>>(nullptr, pos, w_geo1, b_geo1);
    finalize_stats<<<64, 256>>>(g_geo1, be_geo1, 64);
    conv2_kernel<<<CBLKS, 256>>>(w_geo2, b_geo2);
    finalize_stats<<<128, 256>>>(g_geo2, be_geo2, 128);
    final_out<<<NCC, 128>>>(out + (size_t)NCC * 128);
}

// round 10
// speedup vs baseline: 2.3558x; 1.5075x over previous
#include <cuda_runtime.h>
#include <cstdint>
#include <cstddef>

#define B_ 8
#define N_ 16384
#define S_ 1024
#define K_ 32
#define NCC (B_*S_)                 // 8192 centers
#define NROWS (NCC*K_)              // 262144 grouped rows
#define R2_ 0.04f
#define CBLKS (NROWS/64)            // 4096 conv blocks (64 rows each)

// ---------------- device scratch (static; allocation APIs banned) ----------------
__device__ __align__(16) float g_centers[NCC*3];
__device__ int                 g_nbr[NROWS];
__device__ __align__(16) float g_h1[(size_t)NROWS*64];          // 64 MiB (reused sem/geo)
__device__ __align__(16) float g_sum[(size_t)128*CBLKS];        // channel-major partial sums
__device__ __align__(16) float g_ssq[(size_t)128*CBLKS];        // channel-major partial sumsq
__device__ __align__(16) float g_mx[(size_t)NCC*128];           // per-center raw-h2 max
__device__ __align__(16) float g_mn[(size_t)NCC*128];           // per-center raw-h2 min
__device__ __align__(16) float g_a[128];                        // BN scale
__device__ __align__(16) float g_c[128];                        // BN shift

// ---------------- cluster SMEM helpers ----------------
__device__ __forceinline__ uint32_t s2u(const void* p) {
    return (uint32_t)__cvta_generic_to_shared(p);
}
__device__ __forceinline__ uint32_t mapa_u32(uint32_t a, int r) {
    uint32_t ret;
    asm("mapa.shared::cluster.u32 %0, %1, %2;" : "=r"(ret) : "r"(a), "r"(r));
    return ret;
}
__device__ __forceinline__ void st_rem64(uint32_t a, unsigned long long v) {
    asm volatile("st.shared::cluster.u64 [%0], %1;" :: "r"(a), "l"(v) : "memory");
}
__device__ __forceinline__ unsigned long long ld_vol64(const void* p) {
    unsigned long long v;
    asm volatile("ld.volatile.shared.u64 %0, [%1];" : "=l"(v) : "r"(s2u(p)));
    return v;
}

// =====================================================================
// FPS: 8-CTA cluster per batch, 512 thr/CTA, 4 points/thread in regs.
// Cross-CTA exchange via self-validating tagged 8B words (single-copy
// atomic): NO fences, NO flags, NO cluster barrier in the loop.
// Selection order: max dist, then min index (== u64 key; bitwise same).
// =====================================================================
#define FPS_C 8
#define FPS_T 512

__global__ __launch_bounds__(FPS_T, 1) __cluster_dims__(FPS_C, 1, 1)
void fps_kernel(const float* __restrict__ pos) {
    __shared__ unsigned wdist[16];
    __shared__ unsigned widx[16];
    __shared__ float wxs[16], wys[16], wzs[16];
    // rec[slot r][4 words]; word = (payload32 << 32) | tag-bearing lo32.
    // word0: (distbits<<32) | (seq<<16) | (N-idx)   [seq<=1023, N-idx<=16384]
    // word1: (xbits<<32) | seq ; word2: (ybits<<32) | seq ; word3: (zbits<<32) | seq
    __shared__ __align__(16) unsigned long long rec[FPS_C][4];
    __shared__ float sbc[3];

    const int rank = blockIdx.x & (FPS_C - 1);
    const int b    = blockIdx.x >> 3;
    const int tid  = threadIdx.x;
    const int lane = tid & 31, wid = tid >> 5;
    const float* p = pos + (size_t)b * N_ * 3;

    if (tid < FPS_C * 4) ((unsigned long long*)rec)[tid] = 0ull;
    __syncthreads();
    // slots zeroed cluster-wide before any publish
    asm volatile("barrier.cluster.arrive.aligned;" ::: "memory");
    asm volatile("barrier.cluster.wait.aligned;"   ::: "memory");

    float qx[4], qy[4], qz[4], dist[4];
#pragma unroll
    for (int j = 0; j < 4; j++) {
        int g = rank * 2048 + j * FPS_T + tid;
        qx[j] = p[g*3]; qy[j] = p[g*3+1]; qz[j] = p[g*3+2];
        dist[j] = 1e10f;
    }
    float cx = p[0], cy = p[1], cz = p[2];   // far_0 = 0

    for (int s = 0; s < S_; s++) {
        if (rank == 0 && tid == 0) {
            size_t cc = (size_t)b * S_ + s;
            g_centers[cc*3+0] = cx; g_centers[cc*3+1] = cy; g_centers[cc*3+2] = cz;
        }
        if (s == S_ - 1) break;

        // ---- update dists + per-thread argmax (strict > => smallest idx on tie) ----
        float best = -1.0f, bx = 0.f, by = 0.f, bz = 0.f;
        int bidx = 0;
#pragma unroll
        for (int j = 0; j < 4; j++) {
            float dx = qx[j] - cx, dy = qy[j] - cy, dz = qz[j] - cz;
            float d  = fmaf(dz, dz, fmaf(dy, dy, dx * dx));
            float nd = fminf(dist[j], d);
            dist[j]  = nd;
            if (nd > best) { best = nd; bx = qx[j]; by = qy[j]; bz = qz[j];
                             bidx = rank * 2048 + j * FPS_T + tid; }
        }

        // ---- warp reduce: max dist bits, then min idx among holders ----
        unsigned db = __float_as_uint(best);   // dist >= 0 => bits order-isomorphic
        unsigned wd = __reduce_max_sync(0xFFFFFFFFu, db);
        unsigned cand = (db == wd) ? (unsigned)bidx : 0xFFFFFFFFu;
        unsigned wi = __reduce_min_sync(0xFFFFFFFFu, cand);
        if (db == wd && (unsigned)bidx == wi) {   // unique owner lane (idx unique)
            wdist[wid] = wd; widx[wid] = wi;
            wxs[wid] = bx; wys[wid] = by; wzs[wid] = bz;
        }
        __syncthreads();

        const unsigned seq = (unsigned)s + 1u;   // 1..1023, fits 16 bits

        if (wid == 0) {
            // ---- CTA-level reduce over 16 warp records ----
            unsigned d2 = (lane < 16) ? wdist[lane] : 0u;
            unsigned i2 = (lane < 16) ? widx[lane]  : 0xFFFFFFFFu;
            unsigned wd2 = __reduce_max_sync(0xFFFFFFFFu, d2);
            unsigned c2  = (d2 == wd2) ? i2 : 0xFFFFFFFFu;
            unsigned wi2 = __reduce_min_sync(0xFFFFFFFFu, c2);
            unsigned omask = __ballot_sync(0xFFFFFFFFu,
                                           (lane < 16) && d2 == wd2 && i2 == wi2);
            int owner = __ffs(omask) - 1;          // unique (indices unique)

            // ---- publish: lane r pushes 4 tagged words into peer r, slot rank ----
            if (lane < FPS_C) {
                float ox = wxs[owner], oy = wys[owner], oz = wzs[owner];
                unsigned nlo = (unsigned)(N_ - (int)wi2);          // 1..16384
                unsigned long long w0 =
                    ((unsigned long long)wd2 << 32) | (seq << 16) | nlo;
                unsigned long long w1 =
                    ((unsigned long long)__float_as_uint(ox) << 32) | seq;
                unsigned long long w2 =
                    ((unsigned long long)__float_as_uint(oy) << 32) | seq;
                unsigned long long w3 =
                    ((unsigned long long)__float_as_uint(oz) << 32) | seq;
                uint32_t ra = mapa_u32(s2u(&rec[rank][0]), lane);
                st_rem64(ra,      w0);
                st_rem64(ra + 8,  w1);
                st_rem64(ra + 16, w2);
                st_rem64(ra + 24, w3);
            }

            // ---- spin: lane r waits for slot r's 4 words tagged seq ----
            unsigned kd = 0, knlo = 0;
            float fx = 0.f, fy = 0.f, fz = 0.f;
            bool need = (lane < FPS_C);
            for (;;) {
                if (need) {
                    unsigned long long v0 = ld_vol64(&rec[lane][0]);
                    unsigned long long v1 = ld_vol64(&rec[lane][1]);
                    unsigned long long v2 = ld_vol64(&rec[lane][2]);
                    unsigned long long v3 = ld_vol64(&rec[lane][3]);
                    unsigned t0 = ((unsigned)v0 >> 16) & 0xFFFFu;
                    if (t0 == seq && (unsigned)v1 == seq &&
                        (unsigned)v2 == seq && (unsigned)v3 == seq) {
                        kd   = (unsigned)(v0 >> 32);
                        knlo = (unsigned)v0 & 0xFFFFu;
                        fx = __uint_as_float((unsigned)(v1 >> 32));
                        fy = __uint_as_float((unsigned)(v2 >> 32));
                        fz = __uint_as_float((unsigned)(v3 >> 32));
                        need = false;
                    }
                }
                if (__all_sync(0xFFFFFFFFu, !need)) break;
            }

            // ---- combine 8 records: max dist bits, then max (N-idx) = min idx ----
            unsigned hi  = (lane < FPS_C) ? kd : 0u;
            unsigned wdh = __reduce_max_sync(0xFFFFFFFFu, hi);
            unsigned lo2 = (lane < FPS_C && kd == wdh) ? knlo : 0u;
            unsigned wlo = __reduce_max_sync(0xFFFFFFFFu, lo2);
            if (lane < FPS_C && kd == wdh && knlo == wlo) {   // unique lane
                sbc[0] = fx; sbc[1] = fy; sbc[2] = fz;
            }
        }
        __syncthreads();
        cx = sbc[0]; cy = sbc[1]; cz = sbc[2];
    }

    // DSMEM safety: no CTA exits while peers might still address its SMEM.
    asm volatile("barrier.cluster.arrive.aligned;" ::: "memory");
    asm volatile("barrier.cluster.wait.aligned;"   ::: "memory");
}

// =====================================================================
// Ball query: one warp per center, ascending index scan, early exit.
// =====================================================================
__global__ __launch_bounds__(256)
void ballquery_kernel(const float* __restrict__ pos) {
    __shared__ int buf[8][32];
    const int wloc = threadIdx.x >> 5;
    const int lane = threadIdx.x & 31;
    const int cc = blockIdx.x * 8 + wloc;
    const int b = cc >> 10;
    const float* p = pos + (size_t)b * N_ * 3;
    const float cx = g_centers[cc*3], cy = g_centers[cc*3+1], cz = g_centers[cc*3+2];

    int count = 0, first = 0;
    bool haveFirst = false;
    for (int base = 0; base < N_; base += 32) {
        int j = base + lane;
        float x = p[j*3], y = p[j*3+1], z = p[j*3+2];
        float dx = cx - x, dy = cy - y, dz = cz - z;
        float d = fmaf(dz, dz, fmaf(dy, dy, dx * dx));
        bool in = (d <= R2_);
        unsigned m = __ballot_sync(0xFFFFFFFFu, in);
        if (m) {
            if (!haveFirst) { first = base + __ffs(m) - 1; haveFirst = true; }
            int slot = count + __popc(m & ((1u << lane) - 1u));
            if (in && slot < 32) buf[wloc][slot] = j;
            count += __popc(m);
            if (count >= 32) break;
        }
    }
    __syncwarp();
    int v = (lane < count) ? buf[wloc][lane] : first;
    g_nbr[(size_t)cc * 32 + lane] = v;
}

// =====================================================================
// conv1: gather + X[64 x CIN] @ W[CIN x 64] + bias -> raw h1.
// Epilogue: per-block per-channel (sum, sumsq), fixed order, channel-major.
// =====================================================================
template<int CIN, bool GEO>
__global__ __launch_bounds__(256)
void conv1_kernel(const float* __restrict__ feat, const float* __restrict__ pos,
                  const float* __restrict__ W, const float* __restrict__ bias) {
    __shared__ float Xs[64 * CIN];
    __shared__ float Ws[CIN * 64];
    __shared__ float red[16 * 64];
    const int row0 = blockIdx.x * 64;
    const int tid = threadIdx.x;

    for (int i = tid; i < CIN * 64 / 4; i += 256)
        ((float4*)Ws)[i] = ((const float4*)W)[i];

    if (!GEO) {
        for (int i = tid; i < 64 * 16; i += 256) {
            int r = i >> 4, c4 = (i & 15) * 4;
            int row = row0 + r;
            int j = g_nbr[row];
            int b = row >> 15;
            float4 v = *(const float4*)&feat[((size_t)b * N_ + j) * 64 + c4];
            *(float4*)&Xs[r * CIN + c4] = v;
        }
    } else {
        for (int i = tid; i < 64 * CIN; i += 256) {
            int r = i / CIN, c = i - r * CIN;
            int row = row0 + r;
            int cc = row >> 5;
            if (c < 3) {
                Xs[i] = g_centers[cc * 3 + c];
            } else {
                int j = g_nbr[row];
                int b = row >> 15;
                Xs[i] = pos[((size_t)b * N_ + j) * 3 + (c - 3)];
            }
        }
    }
    __syncthreads();

    const int ty = tid >> 4, tx = tid & 15;
    float acc[4][4];
#pragma unroll
    for (int i = 0; i < 4; i++)
#pragma unroll
        for (int j = 0; j < 4; j++) acc[i][j] = 0.0f;

#pragma unroll
    for (int k = 0; k < CIN; k++) {
        float xv[4];
#pragma unroll
        for (int i = 0; i < 4; i++) xv[i] = Xs[(ty * 4 + i) * CIN + k];
        float4 wv = *(const float4*)&Ws[k * 64 + tx * 4];
#pragma unroll
        for (int i = 0; i < 4; i++) {
            acc[i][0] = fmaf(xv[i], wv.x, acc[i][0]);
            acc[i][1] = fmaf(xv[i], wv.y, acc[i][1]);
            acc[i][2] = fmaf(xv[i], wv.z, acc[i][2]);
            acc[i][3] = fmaf(xv[i], wv.w, acc[i][3]);
        }
    }

    float bb[4];
#pragma unroll
    for (int j = 0; j < 4; j++) bb[j] = bias[tx * 4 + j];
    float sl[4] = {0, 0, 0, 0}, ssl[4] = {0, 0, 0, 0};
#pragma unroll
    for (int i = 0; i < 4; i++) {
        int row = row0 + ty * 4 + i;
        float4 hv;
        hv.x = acc[i][0] + bb[0]; hv.y = acc[i][1] + bb[1];
        hv.z = acc[i][2] + bb[2]; hv.w = acc[i][3] + bb[3];
        *(float4*)&g_h1[(size_t)row * 64 + tx * 4] = hv;
        sl[0] += hv.x; ssl[0] += hv.x * hv.x;
        sl[1] += hv.y; ssl[1] += hv.y * hv.y;
        sl[2] += hv.z; ssl[2] += hv.z * hv.z;
        sl[3] += hv.w; ssl[3] += hv.w * hv.w;
    }
#pragma unroll
    for (int j = 0; j < 4; j++) red[ty * 64 + tx * 4 + j] = sl[j];
    __syncthreads();
    float S = 0.0f, SS = 0.0f;
    if (tid < 64) {
#pragma unroll
        for (int t = 0; t < 16; t++) S += red[t * 64 + tid];
    }
    __syncthreads();
#pragma unroll
    for (int j = 0; j < 4; j++) red[ty * 64 + tx * 4 + j] = ssl[j];
    __syncthreads();
    if (tid < 64) {
#pragma unroll
        for (int t = 0; t < 16; t++) SS += red[t * 64 + tid];
        g_sum[(size_t)tid * CBLKS + blockIdx.x] = S;
        g_ssq[(size_t)tid * CBLKS + blockIdx.x] = SS;
    }
}

// =====================================================================
// conv2 (fused): X = relu(a1*h1 + c1); X[64x64] @ W[64x128] + bias.
// h2 never written. Epilogue: channel (sum,sumsq) + per-center max/min.
// =====================================================================
__global__ __launch_bounds__(256)
void conv2_kernel(const float* __restrict__ W, const float* __restrict__ bias) {
    __shared__ float Xs[64 * 64];    // 16 KB (reused as reduce buffer)
    __shared__ float Ws[64 * 128];   // 32 KB
    const int row0 = blockIdx.x * 64;
    const int tid = threadIdx.x;

    for (int i = tid; i < 64 * 128 / 4; i += 256)
        ((float4*)Ws)[i] = ((const float4*)W)[i];
    for (int i = tid; i < 64 * 16; i += 256) {
        int r = i >> 4, c4 = (i & 15) * 4;
        float4 h = *(const float4*)&g_h1[(size_t)(row0 + r) * 64 + c4];
        float4 A = *(const float4*)&g_a[c4];
        float4 C = *(const float4*)&g_c[c4];
        float4 x;
        x.x = fmaxf(0.0f, fmaf(A.x, h.x, C.x));
        x.y = fmaxf(0.0f, fmaf(A.y, h.y, C.y));
        x.z = fmaxf(0.0f, fmaf(A.z, h.z, C.z));
        x.w = fmaxf(0.0f, fmaf(A.w, h.w, C.w));
        *(float4*)&Xs[r * 64 + c4] = x;
    }
    __syncthreads();

    const int ty = tid >> 4, tx = tid & 15;
    float acc[4][8];
#pragma unroll
    for (int i = 0; i < 4; i++)
#pragma unroll
        for (int j = 0; j < 8; j++) acc[i][j] = 0.0f;

#pragma unroll 8
    for (int k = 0; k < 64; k++) {
        float xv[4];
#pragma unroll
        for (int i = 0; i < 4; i++) xv[i] = Xs[(ty * 4 + i) * 64 + k];
        float4 w0 = *(const float4*)&Ws[k * 128 + tx * 8];
        float4 w1 = *(const float4*)&Ws[k * 128 + tx * 8 + 4];
#pragma unroll
        for (int i = 0; i < 4; i++) {
            acc[i][0] = fmaf(xv[i], w0.x, acc[i][0]);
            acc[i][1] = fmaf(xv[i], w0.y, acc[i][1]);
            acc[i][2] = fmaf(xv[i], w0.z, acc[i][2]);
            acc[i][3] = fmaf(xv[i], w0.w, acc[i][3]);
            acc[i][4] = fmaf(xv[i], w1.x, acc[i][4]);
            acc[i][5] = fmaf(xv[i], w1.y, acc[i][5]);
            acc[i][6] = fmaf(xv[i], w1.z, acc[i][6]);
            acc[i][7] = fmaf(xv[i], w1.w, acc[i][7]);
        }
    }

    float bb[8];
#pragma unroll
    for (int j = 0; j < 8; j++) bb[j] = bias[tx * 8 + j];
    float sl[8], ssl[8], mxl[8], mnl[8];
#pragma unroll
    for (int j = 0; j < 8; j++) {
        sl[j] = 0.0f; ssl[j] = 0.0f;
        mxl[j] = -3.402823466e38f; mnl[j] = 3.402823466e38f;
    }
#pragma unroll
    for (int i = 0; i < 4; i++)
#pragma unroll
        for (int j = 0; j < 8; j++) {
            float h = acc[i][j] + bb[j];
            sl[j] += h; ssl[j] += h * h;
            mxl[j] = fmaxf(mxl[j], h); mnl[j] = fminf(mnl[j], h);
        }

    float* red = Xs;
    __syncthreads();

    float S = 0.0f, SS = 0.0f, mA = 0.0f, mB = 0.0f, nA = 0.0f, nB = 0.0f;
#pragma unroll
    for (int j = 0; j < 8; j++) red[ty * 128 + tx * 8 + j] = sl[j];
    __syncthreads();
    if (tid < 128) {
#pragma unroll
        for (int t = 0; t < 16; t++) S += red[t * 128 + tid];
    }
    __syncthreads();
#pragma unroll
    for (int j = 0; j < 8; j++) red[ty * 128 + tx * 8 + j] = ssl[j];
    __syncthreads();
    if (tid < 128) {
#pragma unroll
        for (int t = 0; t < 16; t++) SS += red[t * 128 + tid];
    }
    __syncthreads();
#pragma unroll
    for (int j = 0; j < 8; j++) red[ty * 128 + tx * 8 + j] = mxl[j];
    __syncthreads();
    if (tid < 128) {
        mA = red[0 * 128 + tid]; mB = red[8 * 128 + tid];
#pragma unroll
        for (int t = 1; t < 8; t++) { mA = fmaxf(mA, red[t * 128 + tid]);
                                      mB = fmaxf(mB, red[(8 + t) * 128 + tid]); }
    }
    __syncthreads();
#pragma unroll
    for (int j = 0; j < 8; j++) red[ty * 128 + tx * 8 + j] = mnl[j];
    __syncthreads();
    if (tid < 128) {
        nA = red[0 * 128 + tid]; nB = red[8 * 128 + tid];
#pragma unroll
        for (int t = 1; t < 8; t++) { nA = fminf(nA, red[t * 128 + tid]);
                                      nB = fminf(nB, red[(8 + t) * 128 + tid]); }
        int blk = blockIdx.x;
        g_sum[(size_t)tid * CBLKS + blk] = S;
        g_ssq[(size_t)tid * CBLKS + blk] = SS;
        g_mx[(size_t)(blk * 2 + 0) * 128 + tid] = mA;
        g_mx[(size_t)(blk * 2 + 1) * 128 + tid] = mB;
        g_mn[(size_t)(blk * 2 + 0) * 128 + tid] = nA;
        g_mn[(size_t)(blk * 2 + 1) * 128 + tid] = nB;
    }
}

// =====================================================================
// BN finalize: one block per channel; coalesced channel-major partials;
// fp64 fixed-order reduce -> affine (a, c).
// =====================================================================
__global__ __launch_bounds__(256)
void finalize_stats(const float* __restrict__ gamma,
                    const float* __restrict__ beta, int C) {
    const int ch = blockIdx.x;
    const int t = threadIdx.x;     // 256
    __shared__ double rs[256], rss[256];
    double S = 0.0, SS = 0.0;
#pragma unroll 4
    for (int i = 0; i < 16; i++) {
        int blk = i * 256 + t;     // coalesced + deterministic
        S  += (double)g_sum[(size_t)ch * CBLKS + blk];
        SS += (double)g_ssq[(size_t)ch * CBLKS + blk];
    }
    rs[t] = S; rss[t] = SS;
    __syncthreads();
    for (int off = 128; off; off >>= 1) {
        if (t < off) { rs[t] += rs[t + off]; rss[t] += rss[t + off]; }
        __syncthreads();
    }
    if (t == 0) {
        double inv_n = 1.0 / (double)NROWS;
        double mu  = rs[0] * inv_n;
        double var = rss[0] * inv_n - mu * mu;
        double a = (double)gamma[ch] / sqrt(var + 1e-5);
        g_a[ch] = (float)a;
        g_c[ch] = (float)((double)beta[ch] - mu * a);
    }
}

// =====================================================================
// Output: relu(a * extreme(h2) + c). Affine monotone => commutes with max.
// =====================================================================
__global__ void final_out(float* __restrict__ out) {
    const int cc = blockIdx.x;
    const int ch = threadIdx.x;    // 128
    float a = g_a[ch];
    float ext = (a >= 0.0f) ? g_mx[(size_t)cc * 128 + ch] : g_mn[(size_t)cc * 128 + ch];
    out[(size_t)cc * 128 + ch] = fmaxf(0.0f, fmaf(a, ext, g_c[ch]));
}

// =====================================================================
extern "C" void kernel_launch(void* const* d_in, const int* in_sizes, int n_in,
                              void* d_out, int out_size) {
    const float* pos     = (const float*)d_in[0];
    const float* feat    = (const float*)d_in[1];
    const float* w_sem1  = (const float*)d_in[2];
    const float* b_sem1  = (const float*)d_in[3];
    const float* g_sem1  = (const float*)d_in[4];
    const float* be_sem1 = (const float*)d_in[5];
    const float* w_sem2  = (const float*)d_in[6];
    const float* b_sem2  = (const float*)d_in[7];
    const float* g_sem2  = (const float*)d_in[8];
    const float* be_sem2 = (const float*)d_in[9];
    const float* w_geo1  = (const float*)d_in[10];
    const float* b_geo1  = (const float*)d_in[11];
    const float* g_geo1  = (const float*)d_in[12];
    const float* be_geo1 = (const float*)d_in[13];
    const float* w_geo2  = (const float*)d_in[14];
    const float* b_geo2  = (const float*)d_in[15];
    const float* g_geo2  = (const float*)d_in[16];
    const float* be_geo2 = (const float*)d_in[17];
    float* out = (float*)d_out;

    fps_kernel<<<B_ * FPS_C, FPS_T>>>(pos);
    ballquery_kernel<<<NCC / 8, 256>>>(pos);

    // ---- SEM branch ----
    conv1_kernel<64, false><<<CBLKS, 256>>>(feat, nullptr, w_sem1, b_sem1);
    finalize_stats<<<64, 256>>>(g_sem1, be_sem1, 64);
    conv2_kernel<<<CBLKS, 256>>>(w_sem2, b_sem2);
    finalize_stats<<<128, 256>>>(g_sem2, be_sem2, 128);
    final_out<<<NCC, 128>>>(out);

    // ---- GEO branch (reuses scratch sequentially; stream-ordered) ----
    conv1_kernel<6, true><<<CBLKS, 256>>>(nullptr, pos, w_geo1, b_geo1);
    finalize_stats<<<64, 256>>>(g_geo1, be_geo1, 64);
    conv2_kernel<<<CBLKS, 256>>>(w_geo2, b_geo2);
    finalize_stats<<<128, 256>>>(g_geo2, be_geo2, 128);
    final_out<<<NCC, 128>>>(out + (size_t)NCC * 128);
}